// round 4
// baseline (speedup 1.0000x reference)
#include <cuda_runtime.h>
#include <cuda_bf16.h>
#include <math.h>
#include <stdint.h>

// ---------------------------------------------------------------------------
// Problem dims (fixed by setup_inputs)
// ---------------------------------------------------------------------------
#define BB     2
#define NN     2
#define LL     1024
#define DM     512
#define DI     512
#define DS     16
#define DC     4
#define KK     4
#define DTR    32
#define NF     9
#define SO     3

#define M_IN   (BB*NN*LL)          // 4096
#define K_INP  (DM*NF)             // 4608
#define K_OUTP (2*DI*NF)           // 9216
#define O_IN   (2*DI)              // 1024
#define O_X    (DTR + 2*DS)        // 64
#define O_OUT  DM                  // 512
#define M_XS   (BB*KK*LL)          // 8192 (scan rows; GEMMs use 4096)

// ---------------------------------------------------------------------------
// Scratch (__device__ globals: allocation-free)
// Feature rows store [Fh(K) | Fl(K)]; weight rows store [Wh(K) | Wl(K)].
// ---------------------------------------------------------------------------
__device__ __nv_bfloat16 g_Fb [4096ull * (2 * K_OUTP)];  // max plane: 4096 x 18432
__device__ __nv_bfloat16 g_Wb [1024ull * (2 * K_INP)];   // 1024x9216 == 512x18432
__device__ __nv_bfloat16 g_Wbx[64ull * (2 * K_INP)];
__device__ float g_xz   [M_IN * O_IN];                   // (B,N,L,1024) = [x|z]
__device__ float g_xs   [M_IN * DI];                     // (B,2,L,512) fwd only
__device__ float g_xdbl [M_IN * O_X];                    // (B,2,L,64)
__device__ float g_delta[M_XS * DI];                     // (B,4,L,512)
__device__ float g_y    [M_XS * DI];
__device__ float g_cat  [M_IN * O_IN];

// ---------------------------------------------------------------------------
// Helpers
// ---------------------------------------------------------------------------
__device__ __forceinline__ uint32_t smem_u32(const void* p) {
    uint32_t a;
    asm("{ .reg .u64 t; cvta.to.shared.u64 t, %1; cvt.u32.u64 %0, t; }"
        : "=r"(a) : "l"(p));
    return a;
}
#define CP_ASYNC16(dst, src) \
    asm volatile("cp.async.cg.shared.global [%0], [%1], 16;" :: "r"(dst), "l"(src))

__device__ __forceinline__ void ldsm_x4(uint32_t* r, uint32_t addr) {
    asm volatile("ldmatrix.sync.aligned.m8n8.x4.shared.b16 {%0,%1,%2,%3}, [%4];"
                 : "=r"(r[0]), "=r"(r[1]), "=r"(r[2]), "=r"(r[3]) : "r"(addr));
}
__device__ __forceinline__ void mma_bf16(float* c, const uint32_t* a, const uint32_t* b) {
    asm volatile(
        "mma.sync.aligned.m16n8k16.row.col.f32.bf16.bf16.f32 "
        "{%0,%1,%2,%3}, {%4,%5,%6,%7}, {%8,%9}, {%0,%1,%2,%3};"
        : "+f"(c[0]), "+f"(c[1]), "+f"(c[2]), "+f"(c[3])
        : "r"(a[0]), "r"(a[1]), "r"(a[2]), "r"(a[3]), "r"(b[0]), "r"(b[1]));
}

__device__ __forceinline__ float silu_f(float x) { return x / (1.0f + expf(-x)); }
__device__ __forceinline__ float softplus_f(float x) {
    return fmaxf(x, 0.0f) + log1pf(expf(-fabsf(x)));
}
__device__ __forceinline__ void split_bf16(float v, __nv_bfloat16& hi, __nv_bfloat16& lo) {
    hi = __float2bfloat16(v);
    lo = __float2bfloat16(v - __bfloat162float(hi));
}

// ---------------------------------------------------------------------------
// bf16 mma.sync GEMM with virtual 3-term hi/lo fold over K:
//   C = Ah*Bh^T + Al*Bh^T + Ah*Bl^T
// A rows: [Ah(K)|Al(K)] @ lda; B rows: [Bh(K)|Bl(K)] @ ldb (N x 2K, row-major).
// BM=128, BK=64 bf16, double-buffered cp.async, ldmatrix fragments.
// ---------------------------------------------------------------------------
template <int BN, int WARPS_M, int WARPS_N>
__global__ __launch_bounds__(256)
void bf16_gemm3(const __nv_bfloat16* __restrict__ A,
                const __nv_bfloat16* __restrict__ B,
                float* __restrict__ C, int Kun, int lda, int ldb, int ldc) {
    constexpr int BM = 128, BK = 64;
    constexpr int WMr = BM / WARPS_M;    // warp rows
    constexpr int WNr = BN / WARPS_N;    // warp cols
    constexpr int MT  = WMr / 16;
    constexpr int NT  = WNr / 8;
    constexpr int STR = BK + 8;          // 72 elems = 144 B row stride
    constexpr int ABYTES = BM * STR * 2;
    constexpr int BBYTES = BN * STR * 2;

    extern __shared__ char smem[];
    const uint32_t s0 = smem_u32(smem);
    const uint32_t sA[2] = { s0, s0 + ABYTES };
    const uint32_t sB[2] = { s0 + 2 * ABYTES, s0 + 2 * ABYTES + BBYTES };

    const int tid  = threadIdx.x;
    const int wid  = tid >> 5;
    const int lane = tid & 31;
    const int wm   = wid / WARPS_N;
    const int wn   = wid % WARPS_N;
    const int g    = lane >> 2;
    const int t4   = lane & 3;
    const int bm0  = blockIdx.y * BM;
    const int bn0  = blockIdx.x * BN;

    // per-lane ldmatrix base offsets (bytes) within a tile buffer
    const uint32_t aoff = (uint32_t)((wm * WMr + (lane & 15)) * (STR * 2)
                                     + (((lane >> 4) << 3) << 1));
    const uint32_t boff = (uint32_t)((wn * WNr + ((lane >> 4) << 3) + (lane & 7)) * (STR * 2)
                                     + ((((lane >> 3) & 1) << 3) << 1));

    float acc[MT][NT][4];
#pragma unroll
    for (int i = 0; i < MT; i++)
#pragma unroll
        for (int j = 0; j < NT; j++)
#pragma unroll
            for (int r = 0; r < 4; r++) acc[i][j][r] = 0.0f;

    const int cpt = Kun / BK;            // chunks per term
    const int nchunks = 3 * cpt;

    auto load_chunk = [&](int buf, int c) {
        const int term = c / cpt;
        const int kof  = (c - term * cpt) * BK;
        const __nv_bfloat16* Ap = A + (term == 1 ? Kun : 0) + kof;
        const __nv_bfloat16* Bp = B + (term == 2 ? Kun : 0) + kof;
#pragma unroll 4
        for (int i = tid; i < BM * 8; i += 256) {
            int r = i >> 3, seg = i & 7;
            const char* src = (const char*)(Ap + (size_t)(bm0 + r) * lda) + seg * 16;
            CP_ASYNC16(sA[buf] + (uint32_t)(r * (STR * 2) + seg * 16), src);
        }
#pragma unroll 4
        for (int i = tid; i < BN * 8; i += 256) {
            int r = i >> 3, seg = i & 7;
            const char* src = (const char*)(Bp + (size_t)(bn0 + r) * ldb) + seg * 16;
            CP_ASYNC16(sB[buf] + (uint32_t)(r * (STR * 2) + seg * 16), src);
        }
        asm volatile("cp.async.commit_group;" ::: "memory");
    };

    load_chunk(0, 0);

    for (int c = 0; c < nchunks; c++) {
        int buf = c & 1;
        if (c + 1 < nchunks) {
            load_chunk(buf ^ 1, c + 1);
            asm volatile("cp.async.wait_group 1;" ::: "memory");
        } else {
            asm volatile("cp.async.wait_group 0;" ::: "memory");
        }
        __syncthreads();

#pragma unroll
        for (int kk = 0; kk < BK; kk += 16) {
            uint32_t af[MT][4];
#pragma unroll
            for (int mt = 0; mt < MT; mt++)
                ldsm_x4(af[mt], sA[buf] + aoff + (uint32_t)(mt * 16 * STR * 2 + kk * 2));
            uint32_t bq[NT / 2][4];
#pragma unroll
            for (int p = 0; p < NT / 2; p++)
                ldsm_x4(bq[p], sB[buf] + boff + (uint32_t)(p * 16 * STR * 2 + kk * 2));
#pragma unroll
            for (int mt = 0; mt < MT; mt++)
#pragma unroll
                for (int p = 0; p < NT / 2; p++) {
                    mma_bf16(acc[mt][2 * p],     af[mt], &bq[p][0]);
                    mma_bf16(acc[mt][2 * p + 1], af[mt], &bq[p][2]);
                }
        }
        __syncthreads();
    }

    // epilogue
#pragma unroll
    for (int mt = 0; mt < MT; mt++) {
#pragma unroll
        for (int nt = 0; nt < NT; nt++) {
            int r = bm0 + wm * WMr + mt * 16 + g;
            int cc = bn0 + wn * WNr + nt * 8 + 2 * t4;
            *(float2*)&C[(size_t)r * ldc + cc]       = make_float2(acc[mt][nt][0], acc[mt][nt][1]);
            *(float2*)&C[(size_t)(r + 8) * ldc + cc] = make_float2(acc[mt][nt][2], acc[mt][nt][3]);
        }
    }
}

// ---------------------------------------------------------------------------
// Feature expansion + hi/lo split:  row -> [Fh(K) | Fl(K)] bf16
// ---------------------------------------------------------------------------
__global__ void features_hl(const float* __restrict__ src,
                            __nv_bfloat16* __restrict__ dst, int Mrows, int I) {
    int idx = blockIdx.x * blockDim.x + threadIdx.x;
    if (idx >= Mrows * I) return;
    int row = idx / I, i = idx % I;
    float x = src[idx];

    float g[12];
#pragma unroll
    for (int t = 0; t < 12; t++) g[t] = (float)(t - 3) * 0.4f - 1.0f;
    float b[11];
#pragma unroll
    for (int t = 0; t < 11; t++)
        b[t] = (x >= g[t] && x < g[t + 1]) ? 1.0f : 0.0f;
#pragma unroll
    for (int k = 1; k <= SO; k++) {
#pragma unroll
        for (int t = 0; t < 11; t++) {
            if (t < 11 - k) {
                float a1 = (x - g[t]) / (g[t + k] - g[t]);
                float a2 = (g[t + k + 1] - x) / (g[t + k + 1] - g[t + 1]);
                b[t] = a1 * b[t] + a2 * b[t + 1];
            }
        }
    }

    float f[NF];
    f[0] = silu_f(x);
#pragma unroll
    for (int s = 0; s < 8; s++) f[1 + s] = b[s];

    const int Kd = I * NF;
    __nv_bfloat16* p = dst + (size_t)row * (2 * Kd) + i * NF;
#pragma unroll
    for (int s = 0; s < NF; s++) {
        __nv_bfloat16 hi, lo;
        split_bf16(f[s], hi, lo);
        p[s]      = hi;
        p[Kd + s] = lo;
    }
}

// ---------------------------------------------------------------------------
// Combined KAN weight build + hi/lo split: row o -> [Wh(K) | Wl(K)]
// ---------------------------------------------------------------------------
__global__ void prep_weights_hl(const float* __restrict__ bw,
                                const float* __restrict__ sw,
                                const float* __restrict__ sc,
                                __nv_bfloat16* __restrict__ Wb, int O, int I) {
    int idx = blockIdx.x * blockDim.x + threadIdx.x;
    if (idx >= O * I) return;
    int o = idx / I, i = idx % I;
    float scv = sc[o * I + i];

    float w[NF];
    w[0] = bw[o * I + i];
#pragma unroll
    for (int s = 0; s < 8; s++) w[1 + s] = sw[(o * I + i) * 8 + s] * scv;

    const int Kd = I * NF;
    __nv_bfloat16* p = Wb + (size_t)o * (2 * Kd) + i * NF;
#pragma unroll
    for (int s = 0; s < NF; s++) {
        __nv_bfloat16 hi, lo;
        split_bf16(w[s], hi, lo);
        p[s]      = hi;
        p[Kd + s] = lo;
    }
}

// ---------------------------------------------------------------------------
// Causal depthwise conv (k=4) + bias + SiLU -> xs4 (forward only)
// ---------------------------------------------------------------------------
__global__ void conv_silu_kernel(const float* __restrict__ xz,
                                 const float* __restrict__ cw,
                                 const float* __restrict__ cb,
                                 float* __restrict__ xs) {
    int idx = blockIdx.x * blockDim.x + threadIdx.x;
    if (idx >= M_IN * DI) return;
    int d = idx % DI;
    int t = (idx / DI) % LL;
    int bn = idx / (DI * LL);

    float w0 = cw[d * DC + 0], w1 = cw[d * DC + 1];
    float w2 = cw[d * DC + 2], w3 = cw[d * DC + 3];

    const float* xr = xz + ((size_t)bn * LL) * O_IN + d;
    float acc = cb[d];
    if (t >= 3) acc += xr[(size_t)(t - 3) * O_IN] * w0;
    if (t >= 2) acc += xr[(size_t)(t - 2) * O_IN] * w1;
    if (t >= 1) acc += xr[(size_t)(t - 1) * O_IN] * w2;
    acc += xr[(size_t)t * O_IN] * w3;
    xs[((size_t)bn * LL + t) * DI + d] = silu_f(acc);
}

// ---------------------------------------------------------------------------
// delta8[r8][d] = softplus( dot(xdbl4[r4][0:32], dt_w[d]) + dt_bias[k][d] )
// r4 maps dir k>=2 to the reversed forward row.
// ---------------------------------------------------------------------------
__global__ void dt_delta_kernel(const float* __restrict__ xdbl,
                                const float* __restrict__ dtw,
                                const float* __restrict__ dt_bias,
                                float* __restrict__ delta) {
    int idx = blockIdx.x * blockDim.x + threadIdx.x;
    if (idx >= M_XS * DI) return;
    int d  = idx % DI;
    int r8 = idx / DI;
    int t  = r8 % LL;
    int k  = (r8 / LL) % KK;
    int b  = r8 / (LL * KK);
    int tt = (k < 2) ? t : (LL - 1 - t);
    size_t r4 = (size_t)(b * 2 + (k & 1)) * LL + tt;

    const float* xr = xdbl + r4 * O_X;
    const float* wr = dtw + (size_t)d * DTR;
    float acc = dt_bias[k * DI + d];
#pragma unroll
    for (int j = 0; j < DTR; j++) acc += xr[j] * __ldg(&wr[j]);
    delta[idx] = softplus_f(acc);
}

// ---------------------------------------------------------------------------
// Selective scan; u and B/C read from forward buffers via row mapping.
// ---------------------------------------------------------------------------
__global__ __launch_bounds__(512)
void scan_kernel(const float* __restrict__ xs,
                 const float* __restrict__ delta,
                 const float* __restrict__ xdbl,
                 const float* __restrict__ A_logs,
                 const float* __restrict__ Ds,
                 float* __restrict__ y) {
    int bk   = blockIdx.x >> 2;          // b*4+k
    int dblk = blockIdx.x & 3;
    int tid  = threadIdx.x;
    int dl_  = tid >> 2;
    int ng   = tid & 3;
    int d    = dblk * 128 + dl_;
    int kdir = bk & 3;
    int b    = bk >> 2;
    const size_t fwdbase = (size_t)(b * 2 + (kdir & 1)) * LL;

    float A[4], h[4];
#pragma unroll
    for (int j = 0; j < 4; j++) {
        A[j] = -expf(A_logs[((size_t)(kdir * DI + d)) * DS + ng * 4 + j]);
        h[j] = 0.0f;
    }
    float Dv = Ds[kdir * DI + d];

    const size_t rowbase = (size_t)bk * LL;
    for (int t = 0; t < LL; t++) {
        size_t r8 = rowbase + t;
        int tt = (kdir < 2) ? t : (LL - 1 - t);
        size_t r4 = fwdbase + tt;
        float dl = delta[r8 * DI + d];
        float u  = xs[r4 * DI + d];
        float du = dl * u;
        const float* Bp = xdbl + r4 * O_X + DTR + ng * 4;
        const float* Cp = Bp + DS;
        float cy = 0.0f;
#pragma unroll
        for (int j = 0; j < 4; j++) {
            float e = __expf(dl * A[j]);
            h[j] = h[j] * e + du * __ldg(&Bp[j]);
            cy += h[j] * __ldg(&Cp[j]);
        }
        cy += __shfl_xor_sync(0xffffffffu, cy, 1);
        cy += __shfl_xor_sync(0xffffffffu, cy, 2);
        if (ng == 0) y[r8 * DI + d] = cy + u * Dv;
    }
}

// ---------------------------------------------------------------------------
// Merge fwd/bwd scans and concat with z
// ---------------------------------------------------------------------------
__global__ void merge_kernel(const float* __restrict__ y,
                             const float* __restrict__ xz,
                             float* __restrict__ cat) {
    int idx = blockIdx.x * blockDim.x + threadIdx.x;
    if (idx >= M_IN * DI) return;
    int d = idx % DI;
    int t = (idx / DI) % LL;
    int bn = idx / (DI * LL);
    int b = bn / NN, n = bn % NN;

    float yf = y[((size_t)((b * KK + n) * LL + t)) * DI + d];
    float yb = y[((size_t)((b * KK + 2 + n) * LL + (LL - 1 - t))) * DI + d];
    size_t row = (size_t)bn * LL + t;
    cat[row * O_IN + d]      = yf + yb;
    cat[row * O_IN + DI + d] = xz[row * O_IN + DI + d];
}

// ---------------------------------------------------------------------------
// Launch
// ---------------------------------------------------------------------------
static inline int cdiv(int a, int b) { return (a + b - 1) / b; }

extern "C" void kernel_launch(void* const* d_in, const int* in_sizes, int n_in,
                              void* d_out, int out_size) {
    const float* hs      = (const float*)d_in[0];
    const float* in_bw   = (const float*)d_in[1];
    const float* in_sw   = (const float*)d_in[2];
    const float* in_sc   = (const float*)d_in[3];
    const float* conv_w  = (const float*)d_in[4];
    const float* conv_b  = (const float*)d_in[5];
    const float* x_bw    = (const float*)d_in[6];
    const float* x_sw    = (const float*)d_in[7];
    const float* x_sc    = (const float*)d_in[8];
    const float* dt_w    = (const float*)d_in[9];
    const float* dt_bias = (const float*)d_in[10];
    const float* A_logs  = (const float*)d_in[11];
    const float* Ds      = (const float*)d_in[12];
    const float* out_bw  = (const float*)d_in[13];
    const float* out_sw  = (const float*)d_in[14];
    const float* out_sc  = (const float*)d_in[15];
    float* out = (float*)d_out;

    __nv_bfloat16 *Fb, *Wb, *Wbx;
    float *xz, *xs, *xdbl, *delta, *yb, *cat;
    cudaGetSymbolAddress((void**)&Fb,    g_Fb);
    cudaGetSymbolAddress((void**)&Wb,    g_Wb);
    cudaGetSymbolAddress((void**)&Wbx,   g_Wbx);
    cudaGetSymbolAddress((void**)&xz,    g_xz);
    cudaGetSymbolAddress((void**)&xs,    g_xs);
    cudaGetSymbolAddress((void**)&xdbl,  g_xdbl);
    cudaGetSymbolAddress((void**)&delta, g_delta);
    cudaGetSymbolAddress((void**)&yb,    g_y);
    cudaGetSymbolAddress((void**)&cat,   g_cat);

    // dynamic smem: 2 A bufs (128x72x2B) + 2 B bufs (BNx72x2B)
    const int SM128 = 2 * (128 * 72 * 2) + 2 * (128 * 72 * 2);  // 73728
    const int SM64  = 2 * (128 * 72 * 2) + 2 * (64 * 72 * 2);   // 55296
    cudaFuncSetAttribute((const void*)bf16_gemm3<128, 4, 2>,
                         cudaFuncAttributeMaxDynamicSharedMemorySize, SM128);
    cudaFuncSetAttribute((const void*)bf16_gemm3<64, 8, 1>,
                         cudaFuncAttributeMaxDynamicSharedMemorySize, SM64);

    const int TPB = 256;

    // ---- in-proj KAN: xz = KAN(hidden_states) ----
    prep_weights_hl<<<cdiv(O_IN * DM, TPB), TPB>>>(in_bw, in_sw, in_sc, Wb, O_IN, DM);
    features_hl<<<cdiv(M_IN * DM, TPB), TPB>>>(hs, Fb, M_IN, DM);
    {
        dim3 grid(O_IN / 128, M_IN / 128);   // 8 x 32
        bf16_gemm3<128, 4, 2><<<grid, 256, SM128>>>(Fb, Wb, xz, K_INP,
                                                    2 * K_INP, 2 * K_INP, O_IN);
    }

    // ---- conv + silu -> xs (forward only) ----
    conv_silu_kernel<<<cdiv(M_IN * DI, TPB), TPB>>>(xz, conv_w, conv_b, xs);

    // ---- x-proj KAN on forward rows only (M=4096) ----
    prep_weights_hl<<<cdiv(O_X * DI, TPB), TPB>>>(x_bw, x_sw, x_sc, Wbx, O_X, DI);
    features_hl<<<cdiv(M_IN * DI, TPB), TPB>>>(xs, Fb, M_IN, DI);
    {
        dim3 grid(1, M_IN / 128);            // 1 x 32
        bf16_gemm3<64, 8, 1><<<grid, 256, SM64>>>(Fb, Wbx, xdbl, K_INP,
                                                  2 * K_INP, 2 * K_INP, O_X);
    }

    // ---- delta = softplus(dt @ dt_w^T + bias) for all 4 dirs ----
    dt_delta_kernel<<<cdiv(M_XS * DI, TPB), TPB>>>(xdbl, dt_w, dt_bias, delta);

    // ---- selective scan (+ u*D) ----
    scan_kernel<<<32, 512>>>(xs, delta, xdbl, A_logs, Ds, yb);

    // ---- merge fwd/bwd, concat z ----
    merge_kernel<<<cdiv(M_IN * DI, TPB), TPB>>>(yb, xz, cat);

    // ---- out-proj KAN: out = KAN(cat) ----
    prep_weights_hl<<<cdiv(O_OUT * O_IN, TPB), TPB>>>(out_bw, out_sw, out_sc, Wb, O_OUT, O_IN);
    features_hl<<<cdiv(M_IN * O_IN, TPB), TPB>>>(cat, Fb, M_IN, O_IN);
    {
        dim3 grid(O_OUT / 128, M_IN / 128);  // 4 x 32
        bf16_gemm3<128, 4, 2><<<grid, 256, SM128>>>(Fb, Wb, out, K_OUTP,
                                                    2 * K_OUTP, 2 * K_OUTP, O_OUT);
    }
}

// round 5
// speedup vs baseline: 1.1781x; 1.1781x over previous
#include <cuda_runtime.h>
#include <cuda_bf16.h>
#include <math.h>
#include <stdint.h>

// ---------------------------------------------------------------------------
// Problem dims (fixed by setup_inputs)
// ---------------------------------------------------------------------------
#define BB     2
#define NN     2
#define LL     1024
#define DM     512
#define DI     512
#define DS     16
#define DC     4
#define KK     4
#define DTR    32
#define NF     9
#define SO     3

#define M_IN   (BB*NN*LL)          // 4096
#define K_INP  (DM*NF)             // 4608
#define K_OUTP (2*DI*NF)           // 9216
#define O_IN   (2*DI)              // 1024
#define O_X    (DTR + 2*DS)        // 64
#define O_OUT  DM                  // 512
#define M_XS   (BB*KK*LL)          // 8192

#define XSPLIT 4                   // K-split factor for x-proj GEMM

// ---------------------------------------------------------------------------
// Scratch (__device__ globals: allocation-free)
// ---------------------------------------------------------------------------
__device__ __nv_bfloat16 g_Fb [4096ull * (2 * K_OUTP)];
__device__ __nv_bfloat16 g_Wb [1024ull * (2 * K_INP)];
__device__ __nv_bfloat16 g_Wbx[64ull * (2 * K_INP)];
__device__ float g_xz   [M_IN * O_IN];
__device__ float g_xs   [M_IN * DI];
__device__ float g_xpart[XSPLIT][M_IN * O_X];
__device__ float g_xdbl [M_IN * O_X];
__device__ float g_delta[M_XS * DI];
__device__ float g_y    [M_XS * DI];
__device__ float g_cat  [M_IN * O_IN];
__device__ float g_dtwT [DTR * DI];

// ---------------------------------------------------------------------------
// Helpers
// ---------------------------------------------------------------------------
__device__ __forceinline__ uint32_t smem_u32(const void* p) {
    uint32_t a;
    asm("{ .reg .u64 t; cvta.to.shared.u64 t, %1; cvt.u32.u64 %0, t; }"
        : "=r"(a) : "l"(p));
    return a;
}
#define CP_ASYNC16(dst, src) \
    asm volatile("cp.async.cg.shared.global [%0], [%1], 16;" :: "r"(dst), "l"(src))

__device__ __forceinline__ void ldsm_x4(uint32_t* r, uint32_t addr) {
    asm volatile("ldmatrix.sync.aligned.m8n8.x4.shared.b16 {%0,%1,%2,%3}, [%4];"
                 : "=r"(r[0]), "=r"(r[1]), "=r"(r[2]), "=r"(r[3]) : "r"(addr));
}
__device__ __forceinline__ void mma_bf16(float* c, const uint32_t* a, const uint32_t* b) {
    asm volatile(
        "mma.sync.aligned.m16n8k16.row.col.f32.bf16.bf16.f32 "
        "{%0,%1,%2,%3}, {%4,%5,%6,%7}, {%8,%9}, {%0,%1,%2,%3};"
        : "+f"(c[0]), "+f"(c[1]), "+f"(c[2]), "+f"(c[3])
        : "r"(a[0]), "r"(a[1]), "r"(a[2]), "r"(a[3]), "r"(b[0]), "r"(b[1]));
}

__device__ __forceinline__ float silu_f(float x) { return x / (1.0f + expf(-x)); }
__device__ __forceinline__ float softplus_f(float x) {
    return fmaxf(x, 0.0f) + log1pf(expf(-fabsf(x)));
}
__device__ __forceinline__ void split_bf16(float v, __nv_bfloat16& hi, __nv_bfloat16& lo) {
    hi = __float2bfloat16(v);
    lo = __float2bfloat16(v - __bfloat162float(hi));
}

// ---------------------------------------------------------------------------
// bf16 mma.sync GEMM, virtual 3-term hi/lo fold over K:
//   C = Ah*Bh^T + Al*Bh^T + Ah*Bl^T
// A rows: [Ah(K)|Al(K)] @ lda; B rows: [Bh(K)|Bl(K)] @ ldb.
// blockIdx.z picks a chunk range [z*cpb, min(3*cpt,(z+1)*cpb)) and writes its
// own output plane C + z*zsz (zsz=0 when unsplit).
// ---------------------------------------------------------------------------
template <int BN, int WARPS_M, int WARPS_N>
__global__ __launch_bounds__(256, 2)
void bf16_gemm3(const __nv_bfloat16* __restrict__ A,
                const __nv_bfloat16* __restrict__ B,
                float* __restrict__ C, int Kun, int lda, int ldb, int ldc,
                int csplit, size_t zsz) {
    constexpr int BM = 128, BK = 64;
    constexpr int WMr = BM / WARPS_M;
    constexpr int WNr = BN / WARPS_N;
    constexpr int MT  = WMr / 16;
    constexpr int NT  = WNr / 8;
    constexpr int STR = BK + 8;          // 72 elems = 144 B row stride
    constexpr int ABYTES = BM * STR * 2;
    constexpr int BBYTES = BN * STR * 2;

    extern __shared__ char smem[];
    const uint32_t s0 = smem_u32(smem);
    const uint32_t sA[2] = { s0, s0 + ABYTES };
    const uint32_t sB[2] = { s0 + 2 * ABYTES, s0 + 2 * ABYTES + BBYTES };

    const int tid  = threadIdx.x;
    const int wid  = tid >> 5;
    const int lane = tid & 31;
    const int wm   = wid / WARPS_N;
    const int wn   = wid % WARPS_N;
    const int g    = lane >> 2;
    const int t4   = lane & 3;
    const int bm0  = blockIdx.y * BM;
    const int bn0  = blockIdx.x * BN;

    const uint32_t aoff = (uint32_t)((wm * WMr + (lane & 15)) * (STR * 2)
                                     + (((lane >> 4) << 3) << 1));
    const uint32_t boff = (uint32_t)((wn * WNr + ((lane >> 4) << 3) + (lane & 7)) * (STR * 2)
                                     + ((((lane >> 3) & 1) << 3) << 1));

    float acc[MT][NT][4];
#pragma unroll
    for (int i = 0; i < MT; i++)
#pragma unroll
        for (int j = 0; j < NT; j++)
#pragma unroll
            for (int r = 0; r < 4; r++) acc[i][j][r] = 0.0f;

    const int cpt = Kun / BK;
    const int total = 3 * cpt;
    const int cpb = (total + csplit - 1) / csplit;
    const int c0 = blockIdx.z * cpb;
    const int c1 = min(total, c0 + cpb);

    auto load_chunk = [&](int buf, int c) {
        const int term = c / cpt;
        const int kof  = (c - term * cpt) * BK;
        const __nv_bfloat16* Ap = A + (term == 1 ? Kun : 0) + kof;
        const __nv_bfloat16* Bp = B + (term == 2 ? Kun : 0) + kof;
#pragma unroll 4
        for (int i = tid; i < BM * 8; i += 256) {
            int r = i >> 3, seg = i & 7;
            const char* src = (const char*)(Ap + (size_t)(bm0 + r) * lda) + seg * 16;
            CP_ASYNC16(sA[buf] + (uint32_t)(r * (STR * 2) + seg * 16), src);
        }
#pragma unroll 4
        for (int i = tid; i < BN * 8; i += 256) {
            int r = i >> 3, seg = i & 7;
            const char* src = (const char*)(Bp + (size_t)(bn0 + r) * ldb) + seg * 16;
            CP_ASYNC16(sB[buf] + (uint32_t)(r * (STR * 2) + seg * 16), src);
        }
        asm volatile("cp.async.commit_group;" ::: "memory");
    };

    load_chunk(0, c0);

    for (int c = c0; c < c1; c++) {
        int buf = (c - c0) & 1;
        if (c + 1 < c1) {
            load_chunk(buf ^ 1, c + 1);
            asm volatile("cp.async.wait_group 1;" ::: "memory");
        } else {
            asm volatile("cp.async.wait_group 0;" ::: "memory");
        }
        __syncthreads();

#pragma unroll
        for (int kk = 0; kk < BK; kk += 16) {
            uint32_t af[MT][4];
#pragma unroll
            for (int mt = 0; mt < MT; mt++)
                ldsm_x4(af[mt], sA[buf] + aoff + (uint32_t)(mt * 16 * STR * 2 + kk * 2));
            uint32_t bq[NT / 2][4];
#pragma unroll
            for (int p = 0; p < NT / 2; p++)
                ldsm_x4(bq[p], sB[buf] + boff + (uint32_t)(p * 16 * STR * 2 + kk * 2));
#pragma unroll
            for (int mt = 0; mt < MT; mt++)
#pragma unroll
                for (int p = 0; p < NT / 2; p++) {
                    mma_bf16(acc[mt][2 * p],     af[mt], &bq[p][0]);
                    mma_bf16(acc[mt][2 * p + 1], af[mt], &bq[p][2]);
                }
        }
        __syncthreads();
    }

    float* Cz = C + (size_t)blockIdx.z * zsz;
#pragma unroll
    for (int mt = 0; mt < MT; mt++) {
#pragma unroll
        for (int nt = 0; nt < NT; nt++) {
            int r = bm0 + wm * WMr + mt * 16 + g;
            int cc = bn0 + wn * WNr + nt * 8 + 2 * t4;
            *(float2*)&Cz[(size_t)r * ldc + cc]       = make_float2(acc[mt][nt][0], acc[mt][nt][1]);
            *(float2*)&Cz[(size_t)(r + 8) * ldc + cc] = make_float2(acc[mt][nt][2], acc[mt][nt][3]);
        }
    }
}

// ---------------------------------------------------------------------------
// Reduce XSPLIT partial planes into xdbl
// ---------------------------------------------------------------------------
__global__ void reduce_parts(const float* __restrict__ parts, float* __restrict__ out) {
    int idx = blockIdx.x * blockDim.x + threadIdx.x;
    if (idx >= M_IN * O_X) return;
    float s = 0.0f;
#pragma unroll
    for (int z = 0; z < XSPLIT; z++) s += parts[(size_t)z * (M_IN * O_X) + idx];
    out[idx] = s;
}

// ---------------------------------------------------------------------------
// Feature expansion + hi/lo split:  row -> [Fh(K) | Fl(K)] bf16
// ---------------------------------------------------------------------------
__global__ void features_hl(const float* __restrict__ src,
                            __nv_bfloat16* __restrict__ dst, int Mrows, int I) {
    int idx = blockIdx.x * blockDim.x + threadIdx.x;
    if (idx >= Mrows * I) return;
    int row = idx / I, i = idx % I;
    float x = src[idx];

    float g[12];
#pragma unroll
    for (int t = 0; t < 12; t++) g[t] = (float)(t - 3) * 0.4f - 1.0f;
    float b[11];
#pragma unroll
    for (int t = 0; t < 11; t++)
        b[t] = (x >= g[t] && x < g[t + 1]) ? 1.0f : 0.0f;
#pragma unroll
    for (int k = 1; k <= SO; k++) {
#pragma unroll
        for (int t = 0; t < 11; t++) {
            if (t < 11 - k) {
                float a1 = (x - g[t]) / (g[t + k] - g[t]);
                float a2 = (g[t + k + 1] - x) / (g[t + k + 1] - g[t + 1]);
                b[t] = a1 * b[t] + a2 * b[t + 1];
            }
        }
    }

    float f[NF];
    f[0] = silu_f(x);
#pragma unroll
    for (int s = 0; s < 8; s++) f[1 + s] = b[s];

    const int Kd = I * NF;
    __nv_bfloat16* p = dst + (size_t)row * (2 * Kd) + i * NF;
#pragma unroll
    for (int s = 0; s < NF; s++) {
        __nv_bfloat16 hi, lo;
        split_bf16(f[s], hi, lo);
        p[s]      = hi;
        p[Kd + s] = lo;
    }
}

// ---------------------------------------------------------------------------
// Combined KAN weight build + hi/lo split: row o -> [Wh(K) | Wl(K)]
// ---------------------------------------------------------------------------
__global__ void prep_weights_hl(const float* __restrict__ bw,
                                const float* __restrict__ sw,
                                const float* __restrict__ sc,
                                __nv_bfloat16* __restrict__ Wb, int O, int I) {
    int idx = blockIdx.x * blockDim.x + threadIdx.x;
    if (idx >= O * I) return;
    int o = idx / I, i = idx % I;
    float scv = sc[o * I + i];

    float w[NF];
    w[0] = bw[o * I + i];
#pragma unroll
    for (int s = 0; s < 8; s++) w[1 + s] = sw[(o * I + i) * 8 + s] * scv;

    const int Kd = I * NF;
    __nv_bfloat16* p = Wb + (size_t)o * (2 * Kd) + i * NF;
#pragma unroll
    for (int s = 0; s < NF; s++) {
        __nv_bfloat16 hi, lo;
        split_bf16(w[s], hi, lo);
        p[s]      = hi;
        p[Kd + s] = lo;
    }
}

// ---------------------------------------------------------------------------
// Causal depthwise conv (k=4) + bias + SiLU -> xs (forward only)
// ---------------------------------------------------------------------------
__global__ void conv_silu_kernel(const float* __restrict__ xz,
                                 const float* __restrict__ cw,
                                 const float* __restrict__ cb,
                                 float* __restrict__ xs) {
    int idx = blockIdx.x * blockDim.x + threadIdx.x;
    if (idx >= M_IN * DI) return;
    int d = idx % DI;
    int t = (idx / DI) % LL;
    int bn = idx / (DI * LL);

    float w0 = cw[d * DC + 0], w1 = cw[d * DC + 1];
    float w2 = cw[d * DC + 2], w3 = cw[d * DC + 3];

    const float* xr = xz + ((size_t)bn * LL) * O_IN + d;
    float acc = cb[d];
    if (t >= 3) acc += xr[(size_t)(t - 3) * O_IN] * w0;
    if (t >= 2) acc += xr[(size_t)(t - 2) * O_IN] * w1;
    if (t >= 1) acc += xr[(size_t)(t - 1) * O_IN] * w2;
    acc += xr[(size_t)t * O_IN] * w3;
    xs[((size_t)bn * LL + t) * DI + d] = silu_f(acc);
}

// ---------------------------------------------------------------------------
// dt_w transpose (512x32 -> 32x512)
// ---------------------------------------------------------------------------
__global__ void transpose_dtw(const float* __restrict__ dtw, float* __restrict__ out) {
    int idx = blockIdx.x * blockDim.x + threadIdx.x;
    if (idx >= DTR * DI) return;
    int d = idx % DI, j = idx / DI;
    out[j * DI + d] = dtw[d * DTR + j];
}

// ---------------------------------------------------------------------------
// delta8[r8][d] = softplus( dot(xdbl4[r4][0:32], dtwT[:,d]) + dt_bias[k][d] )
// ---------------------------------------------------------------------------
__global__ void dt_delta_kernel(const float* __restrict__ xdbl,
                                const float* __restrict__ dtwT,
                                const float* __restrict__ dt_bias,
                                float* __restrict__ delta) {
    int idx = blockIdx.x * blockDim.x + threadIdx.x;
    if (idx >= M_XS * DI) return;
    int d  = idx % DI;
    int r8 = idx / DI;
    int t  = r8 % LL;
    int k  = (r8 / LL) % KK;
    int b  = r8 / (LL * KK);
    int tt = (k < 2) ? t : (LL - 1 - t);
    size_t r4 = (size_t)(b * 2 + (k & 1)) * LL + tt;

    const float* xr = xdbl + r4 * O_X;       // broadcast within warp
    float acc = dt_bias[k * DI + d];
#pragma unroll
    for (int j = 0; j < DTR; j++) acc += xr[j] * __ldg(&dtwT[j * DI + d]);
    delta[idx] = softplus_f(acc);
}

// ---------------------------------------------------------------------------
// Selective scan: 64 blocks; each block = (b,k) x 64 channels; 8 lanes per
// channel hold 2 states each; octet shfl-reduce for y.
// ---------------------------------------------------------------------------
__global__ __launch_bounds__(512)
void scan_kernel(const float* __restrict__ xs,
                 const float* __restrict__ delta,
                 const float* __restrict__ xdbl,
                 const float* __restrict__ A_logs,
                 const float* __restrict__ Ds,
                 float* __restrict__ y) {
    int bk   = blockIdx.x >> 3;          // b*4+k (0..7)
    int dblk = blockIdx.x & 7;           // 0..7
    int tid  = threadIdx.x;
    int dl_  = tid >> 3;                 // 0..63
    int ng   = tid & 7;                  // octet: 2 states each
    int d    = dblk * 64 + dl_;
    int kdir = bk & 3;
    int b    = bk >> 2;
    const size_t fwdbase = (size_t)(b * 2 + (kdir & 1)) * LL;

    float A[2], h[2];
#pragma unroll
    for (int j = 0; j < 2; j++) {
        A[j] = -expf(A_logs[((size_t)(kdir * DI + d)) * DS + ng * 2 + j]);
        h[j] = 0.0f;
    }
    float Dv = Ds[kdir * DI + d];

    const size_t rowbase = (size_t)bk * LL;
    for (int t = 0; t < LL; t++) {
        size_t r8 = rowbase + t;
        int tt = (kdir < 2) ? t : (LL - 1 - t);
        size_t r4 = fwdbase + tt;
        float dl = delta[r8 * DI + d];
        float u  = xs[r4 * DI + d];
        float du = dl * u;
        const float* Bp = xdbl + r4 * O_X + DTR + ng * 2;
        const float* Cp = Bp + DS;
        float cy = 0.0f;
#pragma unroll
        for (int j = 0; j < 2; j++) {
            float e = __expf(dl * A[j]);
            h[j] = h[j] * e + du * __ldg(&Bp[j]);
            cy += h[j] * __ldg(&Cp[j]);
        }
        cy += __shfl_xor_sync(0xffffffffu, cy, 1);
        cy += __shfl_xor_sync(0xffffffffu, cy, 2);
        cy += __shfl_xor_sync(0xffffffffu, cy, 4);
        if (ng == 0) y[r8 * DI + d] = cy + u * Dv;
    }
}

// ---------------------------------------------------------------------------
// Merge fwd/bwd scans and concat with z
// ---------------------------------------------------------------------------
__global__ void merge_kernel(const float* __restrict__ y,
                             const float* __restrict__ xz,
                             float* __restrict__ cat) {
    int idx = blockIdx.x * blockDim.x + threadIdx.x;
    if (idx >= M_IN * DI) return;
    int d = idx % DI;
    int t = (idx / DI) % LL;
    int bn = idx / (DI * LL);
    int b = bn / NN, n = bn % NN;

    float yf = y[((size_t)((b * KK + n) * LL + t)) * DI + d];
    float yb = y[((size_t)((b * KK + 2 + n) * LL + (LL - 1 - t))) * DI + d];
    size_t row = (size_t)bn * LL + t;
    cat[row * O_IN + d]      = yf + yb;
    cat[row * O_IN + DI + d] = xz[row * O_IN + DI + d];
}

// ---------------------------------------------------------------------------
// Launch
// ---------------------------------------------------------------------------
static inline int cdiv(int a, int b) { return (a + b - 1) / b; }

extern "C" void kernel_launch(void* const* d_in, const int* in_sizes, int n_in,
                              void* d_out, int out_size) {
    const float* hs      = (const float*)d_in[0];
    const float* in_bw   = (const float*)d_in[1];
    const float* in_sw   = (const float*)d_in[2];
    const float* in_sc   = (const float*)d_in[3];
    const float* conv_w  = (const float*)d_in[4];
    const float* conv_b  = (const float*)d_in[5];
    const float* x_bw    = (const float*)d_in[6];
    const float* x_sw    = (const float*)d_in[7];
    const float* x_sc    = (const float*)d_in[8];
    const float* dt_w    = (const float*)d_in[9];
    const float* dt_bias = (const float*)d_in[10];
    const float* A_logs  = (const float*)d_in[11];
    const float* Ds      = (const float*)d_in[12];
    const float* out_bw  = (const float*)d_in[13];
    const float* out_sw  = (const float*)d_in[14];
    const float* out_sc  = (const float*)d_in[15];
    float* out = (float*)d_out;

    __nv_bfloat16 *Fb, *Wb, *Wbx;
    float *xz, *xs, *xpart, *xdbl, *delta, *yb, *cat, *dtwT;
    cudaGetSymbolAddress((void**)&Fb,    g_Fb);
    cudaGetSymbolAddress((void**)&Wb,    g_Wb);
    cudaGetSymbolAddress((void**)&Wbx,   g_Wbx);
    cudaGetSymbolAddress((void**)&xz,    g_xz);
    cudaGetSymbolAddress((void**)&xs,    g_xs);
    cudaGetSymbolAddress((void**)&xpart, g_xpart);
    cudaGetSymbolAddress((void**)&xdbl,  g_xdbl);
    cudaGetSymbolAddress((void**)&delta, g_delta);
    cudaGetSymbolAddress((void**)&yb,    g_y);
    cudaGetSymbolAddress((void**)&cat,   g_cat);
    cudaGetSymbolAddress((void**)&dtwT,  g_dtwT);

    const int SM128 = 2 * (128 * 72 * 2) + 2 * (128 * 72 * 2);  // 73728
    const int SM64  = 2 * (128 * 72 * 2) + 2 * (64 * 72 * 2);   // 55296
    cudaFuncSetAttribute((const void*)bf16_gemm3<128, 4, 2>,
                         cudaFuncAttributeMaxDynamicSharedMemorySize, SM128);
    cudaFuncSetAttribute((const void*)bf16_gemm3<64, 8, 1>,
                         cudaFuncAttributeMaxDynamicSharedMemorySize, SM64);

    const int TPB = 256;

    // ---- in-proj KAN: xz = KAN(hidden_states) ----
    prep_weights_hl<<<cdiv(O_IN * DM, TPB), TPB>>>(in_bw, in_sw, in_sc, Wb, O_IN, DM);
    features_hl<<<cdiv(M_IN * DM, TPB), TPB>>>(hs, Fb, M_IN, DM);
    {
        dim3 grid(O_IN / 128, M_IN / 128, 1);   // 8 x 32
        bf16_gemm3<128, 4, 2><<<grid, 256, SM128>>>(Fb, Wb, xz, K_INP,
                                                    2 * K_INP, 2 * K_INP, O_IN, 1, 0);
    }

    // ---- conv + silu -> xs (forward only) ----
    conv_silu_kernel<<<cdiv(M_IN * DI, TPB), TPB>>>(xz, conv_w, conv_b, xs);

    // ---- x-proj KAN on forward rows (M=4096), K-split x4 ----
    prep_weights_hl<<<cdiv(O_X * DI, TPB), TPB>>>(x_bw, x_sw, x_sc, Wbx, O_X, DI);
    features_hl<<<cdiv(M_IN * DI, TPB), TPB>>>(xs, Fb, M_IN, DI);
    {
        dim3 grid(1, M_IN / 128, XSPLIT);       // 128 CTAs
        bf16_gemm3<64, 8, 1><<<grid, 256, SM64>>>(Fb, Wbx, xpart, K_INP,
                                                  2 * K_INP, 2 * K_INP, O_X,
                                                  XSPLIT, (size_t)M_IN * O_X);
    }
    reduce_parts<<<cdiv(M_IN * O_X, TPB), TPB>>>(xpart, xdbl);

    // ---- delta = softplus(dt @ dt_w^T + bias) for all 4 dirs ----
    transpose_dtw<<<cdiv(DTR * DI, TPB), TPB>>>(dt_w, dtwT);
    dt_delta_kernel<<<cdiv(M_XS * DI, TPB), TPB>>>(xdbl, dtwT, dt_bias, delta);

    // ---- selective scan (+ u*D) ----
    scan_kernel<<<64, 512>>>(xs, delta, xdbl, A_logs, Ds, yb);

    // ---- merge fwd/bwd, concat z ----
    merge_kernel<<<cdiv(M_IN * DI, TPB), TPB>>>(yb, xz, cat);

    // ---- out-proj KAN: out = KAN(cat) ----
    prep_weights_hl<<<cdiv(O_OUT * O_IN, TPB), TPB>>>(out_bw, out_sw, out_sc, Wb, O_OUT, O_IN);
    features_hl<<<cdiv(M_IN * O_IN, TPB), TPB>>>(cat, Fb, M_IN, O_IN);
    {
        dim3 grid(O_OUT / 128, M_IN / 128, 1);  // 4 x 32
        bf16_gemm3<128, 4, 2><<<grid, 256, SM128>>>(Fb, Wb, out, K_OUTP,
                                                    2 * K_OUTP, 2 * K_OUTP, O_OUT, 1, 0);
    }
}

// round 6
// speedup vs baseline: 1.2642x; 1.0730x over previous
#include <cuda_runtime.h>
#include <cuda_bf16.h>
#include <math.h>
#include <stdint.h>

// ---------------------------------------------------------------------------
// Problem dims (fixed by setup_inputs)
// ---------------------------------------------------------------------------
#define BB     2
#define NN     2
#define LL     1024
#define DM     512
#define DI     512
#define DS     16
#define DC     4
#define KK     4
#define DTR    32
#define NF     9
#define SO     3

#define M_IN   (BB*NN*LL)          // 4096
#define K_INP  (DM*NF)             // 4608
#define K_OUTP (2*DI*NF)           // 9216
#define O_IN   (2*DI)              // 1024
#define O_X    (DTR + 2*DS)        // 64
#define O_OUT  DM                  // 512
#define M_XS   (BB*KK*LL)          // 8192

#define XSPLIT 4                   // K-split factor for x-proj GEMM
#define OSPLIT 2                   // K-split factor for out-proj GEMM

// ---------------------------------------------------------------------------
// Scratch (__device__ globals: allocation-free)
// ---------------------------------------------------------------------------
__device__ __nv_bfloat16 g_Fb [4096ull * (2 * K_OUTP)];
__device__ __nv_bfloat16 g_Wb [1024ull * (2 * K_INP)];
__device__ __nv_bfloat16 g_Wbx[64ull * (2 * K_INP)];
__device__ float g_xz   [M_IN * O_IN];
__device__ float g_xs   [M_IN * DI];
__device__ float g_xpart[XSPLIT][M_IN * O_X];
__device__ float g_opart[OSPLIT][M_IN * O_OUT];
__device__ float g_xdbl [M_IN * O_X];
__device__ float g_delta[M_XS * DI];
__device__ float g_y    [M_XS * DI];
__device__ float g_cat  [M_IN * O_IN];
__device__ float g_dtwT [DTR * DI];

// ---------------------------------------------------------------------------
// Helpers
// ---------------------------------------------------------------------------
__device__ __forceinline__ uint32_t smem_u32(const void* p) {
    uint32_t a;
    asm("{ .reg .u64 t; cvta.to.shared.u64 t, %1; cvt.u32.u64 %0, t; }"
        : "=r"(a) : "l"(p));
    return a;
}
#define CP_ASYNC16(dst, src) \
    asm volatile("cp.async.cg.shared.global [%0], [%1], 16;" :: "r"(dst), "l"(src))

__device__ __forceinline__ void ldsm_x4(uint32_t* r, uint32_t addr) {
    asm volatile("ldmatrix.sync.aligned.m8n8.x4.shared.b16 {%0,%1,%2,%3}, [%4];"
                 : "=r"(r[0]), "=r"(r[1]), "=r"(r[2]), "=r"(r[3]) : "r"(addr));
}
__device__ __forceinline__ void mma_bf16(float* c, const uint32_t* a, const uint32_t* b) {
    asm volatile(
        "mma.sync.aligned.m16n8k16.row.col.f32.bf16.bf16.f32 "
        "{%0,%1,%2,%3}, {%4,%5,%6,%7}, {%8,%9}, {%0,%1,%2,%3};"
        : "+f"(c[0]), "+f"(c[1]), "+f"(c[2]), "+f"(c[3])
        : "r"(a[0]), "r"(a[1]), "r"(a[2]), "r"(a[3]), "r"(b[0]), "r"(b[1]));
}

__device__ __forceinline__ float silu_f(float x) { return x / (1.0f + expf(-x)); }
__device__ __forceinline__ float softplus_f(float x) {
    return fmaxf(x, 0.0f) + log1pf(expf(-fabsf(x)));
}
__device__ __forceinline__ void split_bf16(float v, __nv_bfloat16& hi, __nv_bfloat16& lo) {
    hi = __float2bfloat16(v);
    lo = __float2bfloat16(v - __bfloat162float(hi));
}

// ---------------------------------------------------------------------------
// bf16 mma.sync GEMM, virtual 3-term hi/lo fold over K:
//   C = Ah*Bh^T + Al*Bh^T + Ah*Bl^T
// 3-stage cp.async ring, one __syncthreads per chunk, loads precede compute.
// blockIdx.z selects chunk range (csplit) and output plane (zsz stride).
// ---------------------------------------------------------------------------
template <int BN, int WARPS_M, int WARPS_N>
__global__ __launch_bounds__(256, 2)
void bf16_gemm3(const __nv_bfloat16* __restrict__ A,
                const __nv_bfloat16* __restrict__ B,
                float* __restrict__ C, int Kun, int lda, int ldb, int ldc,
                int csplit, size_t zsz) {
    constexpr int BM = 128, BK = 64, S = 3;
    constexpr int WMr = BM / WARPS_M;
    constexpr int WNr = BN / WARPS_N;
    constexpr int MT  = WMr / 16;
    constexpr int NT  = WNr / 8;
    constexpr int STR = BK + 8;          // 72 elems = 144 B row stride
    constexpr int ABYTES = BM * STR * 2;
    constexpr int BBYTES = BN * STR * 2;
    constexpr int STAGE  = ABYTES + BBYTES;

    extern __shared__ char smem[];
    const uint32_t s0 = smem_u32(smem);

    const int tid  = threadIdx.x;
    const int wid  = tid >> 5;
    const int lane = tid & 31;
    const int wm   = wid / WARPS_N;
    const int wn   = wid % WARPS_N;
    const int g    = lane >> 2;
    const int t4   = lane & 3;
    const int bm0  = blockIdx.y * BM;
    const int bn0  = blockIdx.x * BN;

    const uint32_t aoff = (uint32_t)((wm * WMr + (lane & 15)) * (STR * 2)
                                     + (((lane >> 4) << 3) << 1));
    const uint32_t boff = (uint32_t)((wn * WNr + ((lane >> 4) << 3) + (lane & 7)) * (STR * 2)
                                     + ((((lane >> 3) & 1) << 3) << 1));

    float acc[MT][NT][4];
#pragma unroll
    for (int i = 0; i < MT; i++)
#pragma unroll
        for (int j = 0; j < NT; j++)
#pragma unroll
            for (int r = 0; r < 4; r++) acc[i][j][r] = 0.0f;

    const int cpt = Kun / BK;
    const int total = 3 * cpt;
    const int cpb = (total + csplit - 1) / csplit;
    const int c0 = blockIdx.z * cpb;
    const int c1 = min(total, c0 + cpb);

    auto load_chunk = [&](int stage, int c) {
        const int term = c / cpt;
        const int kof  = (c - term * cpt) * BK;
        const __nv_bfloat16* Ap = A + (term == 1 ? Kun : 0) + kof;
        const __nv_bfloat16* Bp = B + (term == 2 ? Kun : 0) + kof;
        const uint32_t sA = s0 + stage * STAGE;
        const uint32_t sB = sA + ABYTES;
#pragma unroll 4
        for (int i = tid; i < BM * 8; i += 256) {
            int r = i >> 3, seg = i & 7;
            const char* src = (const char*)(Ap + (size_t)(bm0 + r) * lda) + seg * 16;
            CP_ASYNC16(sA + (uint32_t)(r * (STR * 2) + seg * 16), src);
        }
#pragma unroll 4
        for (int i = tid; i < BN * 8; i += 256) {
            int r = i >> 3, seg = i & 7;
            const char* src = (const char*)(Bp + (size_t)(bn0 + r) * ldb) + seg * 16;
            CP_ASYNC16(sB + (uint32_t)(r * (STR * 2) + seg * 16), src);
        }
        asm volatile("cp.async.commit_group;" ::: "memory");
    };

    // preload S-1 stages
    const int npre = min(S - 1, c1 - c0);
#pragma unroll
    for (int s = 0; s < S - 1; s++)
        if (s < npre) load_chunk(s, c0 + s);

    for (int c = c0; c < c1; c++) {
        const int stage = (c - c0) % S;
        // guarantee the group that loaded `stage` is complete
        if (c == c1 - 1) asm volatile("cp.async.wait_group 0;" ::: "memory");
        else             asm volatile("cp.async.wait_group %0;" :: "n"(S - 2) : "memory");
        __syncthreads();

        if (c + S - 1 < c1) load_chunk((c - c0 + S - 1) % S, c + S - 1);

        const uint32_t sA = s0 + stage * STAGE;
        const uint32_t sB = sA + ABYTES;
#pragma unroll
        for (int kk = 0; kk < BK; kk += 16) {
            uint32_t af[MT][4];
#pragma unroll
            for (int mt = 0; mt < MT; mt++)
                ldsm_x4(af[mt], sA + aoff + (uint32_t)(mt * 16 * STR * 2 + kk * 2));
            uint32_t bq[NT / 2][4];
#pragma unroll
            for (int p = 0; p < NT / 2; p++)
                ldsm_x4(bq[p], sB + boff + (uint32_t)(p * 16 * STR * 2 + kk * 2));
#pragma unroll
            for (int mt = 0; mt < MT; mt++)
#pragma unroll
                for (int p = 0; p < NT / 2; p++) {
                    mma_bf16(acc[mt][2 * p],     af[mt], &bq[p][0]);
                    mma_bf16(acc[mt][2 * p + 1], af[mt], &bq[p][2]);
                }
        }
    }

    float* Cz = C + (size_t)blockIdx.z * zsz;
#pragma unroll
    for (int mt = 0; mt < MT; mt++) {
#pragma unroll
        for (int nt = 0; nt < NT; nt++) {
            int r = bm0 + wm * WMr + mt * 16 + g;
            int cc = bn0 + wn * WNr + nt * 8 + 2 * t4;
            *(float2*)&Cz[(size_t)r * ldc + cc]       = make_float2(acc[mt][nt][0], acc[mt][nt][1]);
            *(float2*)&Cz[(size_t)(r + 8) * ldc + cc] = make_float2(acc[mt][nt][2], acc[mt][nt][3]);
        }
    }
}

// ---------------------------------------------------------------------------
// Reductions for split planes
// ---------------------------------------------------------------------------
__global__ void reduce_parts(const float* __restrict__ parts, float* __restrict__ out) {
    int idx = blockIdx.x * blockDim.x + threadIdx.x;
    if (idx >= M_IN * O_X) return;
    float s = 0.0f;
#pragma unroll
    for (int z = 0; z < XSPLIT; z++) s += parts[(size_t)z * (M_IN * O_X) + idx];
    out[idx] = s;
}
__global__ void reduce_out(const float* __restrict__ parts, float* __restrict__ out) {
    int idx = blockIdx.x * blockDim.x + threadIdx.x;
    if (idx >= M_IN * O_OUT) return;
    out[idx] = parts[idx] + parts[(size_t)(M_IN * O_OUT) + idx];
}

// ---------------------------------------------------------------------------
// Feature expansion + hi/lo split:  row -> [Fh(K) | Fl(K)] bf16
// ---------------------------------------------------------------------------
__global__ void features_hl(const float* __restrict__ src,
                            __nv_bfloat16* __restrict__ dst, int Mrows, int I) {
    int idx = blockIdx.x * blockDim.x + threadIdx.x;
    if (idx >= Mrows * I) return;
    int row = idx / I, i = idx % I;
    float x = src[idx];

    float g[12];
#pragma unroll
    for (int t = 0; t < 12; t++) g[t] = (float)(t - 3) * 0.4f - 1.0f;
    float b[11];
#pragma unroll
    for (int t = 0; t < 11; t++)
        b[t] = (x >= g[t] && x < g[t + 1]) ? 1.0f : 0.0f;
#pragma unroll
    for (int k = 1; k <= SO; k++) {
#pragma unroll
        for (int t = 0; t < 11; t++) {
            if (t < 11 - k) {
                float a1 = (x - g[t]) / (g[t + k] - g[t]);
                float a2 = (g[t + k + 1] - x) / (g[t + k + 1] - g[t + 1]);
                b[t] = a1 * b[t] + a2 * b[t + 1];
            }
        }
    }

    float f[NF];
    f[0] = silu_f(x);
#pragma unroll
    for (int s = 0; s < 8; s++) f[1 + s] = b[s];

    const int Kd = I * NF;
    __nv_bfloat16* p = dst + (size_t)row * (2 * Kd) + i * NF;
#pragma unroll
    for (int s = 0; s < NF; s++) {
        __nv_bfloat16 hi, lo;
        split_bf16(f[s], hi, lo);
        p[s]      = hi;
        p[Kd + s] = lo;
    }
}

// ---------------------------------------------------------------------------
// Combined KAN weight build + hi/lo split: row o -> [Wh(K) | Wl(K)]
// ---------------------------------------------------------------------------
__global__ void prep_weights_hl(const float* __restrict__ bw,
                                const float* __restrict__ sw,
                                const float* __restrict__ sc,
                                __nv_bfloat16* __restrict__ Wb, int O, int I) {
    int idx = blockIdx.x * blockDim.x + threadIdx.x;
    if (idx >= O * I) return;
    int o = idx / I, i = idx % I;
    float scv = sc[o * I + i];

    float w[NF];
    w[0] = bw[o * I + i];
#pragma unroll
    for (int s = 0; s < 8; s++) w[1 + s] = sw[(o * I + i) * 8 + s] * scv;

    const int Kd = I * NF;
    __nv_bfloat16* p = Wb + (size_t)o * (2 * Kd) + i * NF;
#pragma unroll
    for (int s = 0; s < NF; s++) {
        __nv_bfloat16 hi, lo;
        split_bf16(w[s], hi, lo);
        p[s]      = hi;
        p[Kd + s] = lo;
    }
}

// ---------------------------------------------------------------------------
// Causal depthwise conv (k=4) + bias + SiLU -> xs (forward only)
// ---------------------------------------------------------------------------
__global__ void conv_silu_kernel(const float* __restrict__ xz,
                                 const float* __restrict__ cw,
                                 const float* __restrict__ cb,
                                 float* __restrict__ xs) {
    int idx = blockIdx.x * blockDim.x + threadIdx.x;
    if (idx >= M_IN * DI) return;
    int d = idx % DI;
    int t = (idx / DI) % LL;
    int bn = idx / (DI * LL);

    float w0 = cw[d * DC + 0], w1 = cw[d * DC + 1];
    float w2 = cw[d * DC + 2], w3 = cw[d * DC + 3];

    const float* xr = xz + ((size_t)bn * LL) * O_IN + d;
    float acc = cb[d];
    if (t >= 3) acc += xr[(size_t)(t - 3) * O_IN] * w0;
    if (t >= 2) acc += xr[(size_t)(t - 2) * O_IN] * w1;
    if (t >= 1) acc += xr[(size_t)(t - 1) * O_IN] * w2;
    acc += xr[(size_t)t * O_IN] * w3;
    xs[((size_t)bn * LL + t) * DI + d] = silu_f(acc);
}

// ---------------------------------------------------------------------------
// dt_w transpose (512x32 -> 32x512)
// ---------------------------------------------------------------------------
__global__ void transpose_dtw(const float* __restrict__ dtw, float* __restrict__ out) {
    int idx = blockIdx.x * blockDim.x + threadIdx.x;
    if (idx >= DTR * DI) return;
    int d = idx % DI, j = idx / DI;
    out[j * DI + d] = dtw[d * DTR + j];
}

// ---------------------------------------------------------------------------
// delta8[r8][d] = softplus( dot(xdbl4[r4][0:32], dtwT[:,d]) + dt_bias[k][d] )
// ---------------------------------------------------------------------------
__global__ void dt_delta_kernel(const float* __restrict__ xdbl,
                                const float* __restrict__ dtwT,
                                const float* __restrict__ dt_bias,
                                float* __restrict__ delta) {
    int idx = blockIdx.x * blockDim.x + threadIdx.x;
    if (idx >= M_XS * DI) return;
    int d  = idx % DI;
    int r8 = idx / DI;
    int t  = r8 % LL;
    int k  = (r8 / LL) % KK;
    int b  = r8 / (LL * KK);
    int tt = (k < 2) ? t : (LL - 1 - t);
    size_t r4 = (size_t)(b * 2 + (k & 1)) * LL + tt;

    const float* xr = xdbl + r4 * O_X;
    float acc = dt_bias[k * DI + d];
#pragma unroll
    for (int j = 0; j < DTR; j++) acc += xr[j] * __ldg(&dtwT[j * DI + d]);
    delta[idx] = softplus_f(acc);
}

// ---------------------------------------------------------------------------
// Selective scan: 64 blocks; (b,k) x 64 channels; 8 lanes/channel, 2 states.
// ---------------------------------------------------------------------------
__global__ __launch_bounds__(512)
void scan_kernel(const float* __restrict__ xs,
                 const float* __restrict__ delta,
                 const float* __restrict__ xdbl,
                 const float* __restrict__ A_logs,
                 const float* __restrict__ Ds,
                 float* __restrict__ y) {
    int bk   = blockIdx.x >> 3;
    int dblk = blockIdx.x & 7;
    int tid  = threadIdx.x;
    int dl_  = tid >> 3;
    int ng   = tid & 7;
    int d    = dblk * 64 + dl_;
    int kdir = bk & 3;
    int b    = bk >> 2;
    const size_t fwdbase = (size_t)(b * 2 + (kdir & 1)) * LL;

    float A[2], h[2];
#pragma unroll
    for (int j = 0; j < 2; j++) {
        A[j] = -expf(A_logs[((size_t)(kdir * DI + d)) * DS + ng * 2 + j]);
        h[j] = 0.0f;
    }
    float Dv = Ds[kdir * DI + d];

    const size_t rowbase = (size_t)bk * LL;
    for (int t = 0; t < LL; t++) {
        size_t r8 = rowbase + t;
        int tt = (kdir < 2) ? t : (LL - 1 - t);
        size_t r4 = fwdbase + tt;
        float dl = delta[r8 * DI + d];
        float u  = xs[r4 * DI + d];
        float du = dl * u;
        const float* Bp = xdbl + r4 * O_X + DTR + ng * 2;
        const float* Cp = Bp + DS;
        float cy = 0.0f;
#pragma unroll
        for (int j = 0; j < 2; j++) {
            float e = __expf(dl * A[j]);
            h[j] = h[j] * e + du * __ldg(&Bp[j]);
            cy += h[j] * __ldg(&Cp[j]);
        }
        cy += __shfl_xor_sync(0xffffffffu, cy, 1);
        cy += __shfl_xor_sync(0xffffffffu, cy, 2);
        cy += __shfl_xor_sync(0xffffffffu, cy, 4);
        if (ng == 0) y[r8 * DI + d] = cy + u * Dv;
    }
}

// ---------------------------------------------------------------------------
// Merge fwd/bwd scans and concat with z
// ---------------------------------------------------------------------------
__global__ void merge_kernel(const float* __restrict__ y,
                             const float* __restrict__ xz,
                             float* __restrict__ cat) {
    int idx = blockIdx.x * blockDim.x + threadIdx.x;
    if (idx >= M_IN * DI) return;
    int d = idx % DI;
    int t = (idx / DI) % LL;
    int bn = idx / (DI * LL);
    int b = bn / NN, n = bn % NN;

    float yf = y[((size_t)((b * KK + n) * LL + t)) * DI + d];
    float yb = y[((size_t)((b * KK + 2 + n) * LL + (LL - 1 - t))) * DI + d];
    size_t row = (size_t)bn * LL + t;
    cat[row * O_IN + d]      = yf + yb;
    cat[row * O_IN + DI + d] = xz[row * O_IN + DI + d];
}

// ---------------------------------------------------------------------------
// Launch
// ---------------------------------------------------------------------------
static inline int cdiv(int a, int b) { return (a + b - 1) / b; }

extern "C" void kernel_launch(void* const* d_in, const int* in_sizes, int n_in,
                              void* d_out, int out_size) {
    const float* hs      = (const float*)d_in[0];
    const float* in_bw   = (const float*)d_in[1];
    const float* in_sw   = (const float*)d_in[2];
    const float* in_sc   = (const float*)d_in[3];
    const float* conv_w  = (const float*)d_in[4];
    const float* conv_b  = (const float*)d_in[5];
    const float* x_bw    = (const float*)d_in[6];
    const float* x_sw    = (const float*)d_in[7];
    const float* x_sc    = (const float*)d_in[8];
    const float* dt_w    = (const float*)d_in[9];
    const float* dt_bias = (const float*)d_in[10];
    const float* A_logs  = (const float*)d_in[11];
    const float* Ds      = (const float*)d_in[12];
    const float* out_bw  = (const float*)d_in[13];
    const float* out_sw  = (const float*)d_in[14];
    const float* out_sc  = (const float*)d_in[15];
    float* out = (float*)d_out;

    __nv_bfloat16 *Fb, *Wb, *Wbx;
    float *xz, *xs, *xpart, *opart, *xdbl, *delta, *yb, *cat, *dtwT;
    cudaGetSymbolAddress((void**)&Fb,    g_Fb);
    cudaGetSymbolAddress((void**)&Wb,    g_Wb);
    cudaGetSymbolAddress((void**)&Wbx,   g_Wbx);
    cudaGetSymbolAddress((void**)&xz,    g_xz);
    cudaGetSymbolAddress((void**)&xs,    g_xs);
    cudaGetSymbolAddress((void**)&xpart, g_xpart);
    cudaGetSymbolAddress((void**)&opart, g_opart);
    cudaGetSymbolAddress((void**)&xdbl,  g_xdbl);
    cudaGetSymbolAddress((void**)&delta, g_delta);
    cudaGetSymbolAddress((void**)&yb,    g_y);
    cudaGetSymbolAddress((void**)&cat,   g_cat);
    cudaGetSymbolAddress((void**)&dtwT,  g_dtwT);

    // 3-stage smem: stage = A(128x72x2) + B(BNx72x2)
    const int SM128 = 3 * (128 * 72 * 2 + 128 * 72 * 2);  // 110592
    const int SM64  = 3 * (128 * 72 * 2 + 64 * 72 * 2);   //  82944
    cudaFuncSetAttribute((const void*)bf16_gemm3<128, 4, 2>,
                         cudaFuncAttributeMaxDynamicSharedMemorySize, SM128);
    cudaFuncSetAttribute((const void*)bf16_gemm3<64, 8, 1>,
                         cudaFuncAttributeMaxDynamicSharedMemorySize, SM64);

    const int TPB = 256;

    // ---- in-proj KAN: xz = KAN(hidden_states) ----
    prep_weights_hl<<<cdiv(O_IN * DM, TPB), TPB>>>(in_bw, in_sw, in_sc, Wb, O_IN, DM);
    features_hl<<<cdiv(M_IN * DM, TPB), TPB>>>(hs, Fb, M_IN, DM);
    {
        dim3 grid(O_IN / 128, M_IN / 128, 1);   // 256 CTAs
        bf16_gemm3<128, 4, 2><<<grid, 256, SM128>>>(Fb, Wb, xz, K_INP,
                                                    2 * K_INP, 2 * K_INP, O_IN, 1, 0);
    }

    // ---- conv + silu -> xs (forward only) ----
    conv_silu_kernel<<<cdiv(M_IN * DI, TPB), TPB>>>(xz, conv_w, conv_b, xs);

    // ---- x-proj KAN on forward rows (M=4096), K-split x4 ----
    prep_weights_hl<<<cdiv(O_X * DI, TPB), TPB>>>(x_bw, x_sw, x_sc, Wbx, O_X, DI);
    features_hl<<<cdiv(M_IN * DI, TPB), TPB>>>(xs, Fb, M_IN, DI);
    {
        dim3 grid(1, M_IN / 128, XSPLIT);       // 128 CTAs
        bf16_gemm3<64, 8, 1><<<grid, 256, SM64>>>(Fb, Wbx, xpart, K_INP,
                                                  2 * K_INP, 2 * K_INP, O_X,
                                                  XSPLIT, (size_t)M_IN * O_X);
    }
    reduce_parts<<<cdiv(M_IN * O_X, TPB), TPB>>>(xpart, xdbl);

    // ---- delta = softplus(dt @ dt_w^T + bias) for all 4 dirs ----
    transpose_dtw<<<cdiv(DTR * DI, TPB), TPB>>>(dt_w, dtwT);
    dt_delta_kernel<<<cdiv(M_XS * DI, TPB), TPB>>>(xdbl, dtwT, dt_bias, delta);

    // ---- selective scan (+ u*D) ----
    scan_kernel<<<64, 512>>>(xs, delta, xdbl, A_logs, Ds, yb);

    // ---- merge fwd/bwd, concat z ----
    merge_kernel<<<cdiv(M_IN * DI, TPB), TPB>>>(yb, xz, cat);

    // ---- out-proj KAN: out = KAN(cat), K-split x2 ----
    prep_weights_hl<<<cdiv(O_OUT * O_IN, TPB), TPB>>>(out_bw, out_sw, out_sc, Wb, O_OUT, O_IN);
    features_hl<<<cdiv(M_IN * O_IN, TPB), TPB>>>(cat, Fb, M_IN, O_IN);
    {
        dim3 grid(O_OUT / 128, M_IN / 128, OSPLIT);  // 256 CTAs
        bf16_gemm3<128, 4, 2><<<grid, 256, SM128>>>(Fb, Wb, opart, K_OUTP,
                                                    2 * K_OUTP, 2 * K_OUTP, O_OUT,
                                                    OSPLIT, (size_t)M_IN * O_OUT);
    }
    reduce_out<<<cdiv(M_IN * O_OUT, TPB), TPB>>>(opart, out);
}